// round 5
// baseline (speedup 1.0000x reference)
#include <cuda_runtime.h>

// x <- gelu(x + depthwise_conv3d_3x3x3(x)) x8.  [4,32,64,64,64] fp32.

#define CC   32
#define VOL  (64*64*64)
#define RS   72                 // words per slab row
#define SLW  (18*RS)            // words per copy (18 rows)
#define BUFW (2*SLW)            // words per buffer (copyA + shifted copyB)

typedef unsigned long long u64;
typedef unsigned int u32;

// Ping-pong scratches padded TWO planes (prefetch reads up to plane 65).
__device__ float  g_sA[4 * CC * VOL + 8192];
__device__ float  g_sB[4 * CC * VOL + 8192];
__device__ __align__(16) float4 g_zero4 = {0.f, 0.f, 0.f, 0.f};

// ---------- packed f32x2 helpers ----------
__device__ __forceinline__ u64 pack2(float lo, float hi) {
    u64 r; asm("mov.b64 %0, {%1, %2};" : "=l"(r) : "f"(lo), "f"(hi)); return r;
}
__device__ __forceinline__ void unpack2(u64 v, float& lo, float& hi) {
    asm("mov.b64 {%0, %1}, %2;" : "=f"(lo), "=f"(hi) : "l"(v));
}
__device__ __forceinline__ void fma2(u64& acc, u64 a, u64 b) {
    asm("fma.rn.f32x2 %0, %1, %2, %0;" : "+l"(acc) : "l"(a), "l"(b));
}
__device__ __forceinline__ void mul2(u64& d, u64 a, u64 b) {
    asm("mul.rn.f32x2 %0, %1, %2;" : "=l"(d) : "l"(a), "l"(b));
}
__device__ __forceinline__ u64 add2(u64 a, u64 b) {
    u64 r; asm("add.rn.f32x2 %0, %1, %2;" : "=l"(r) : "l"(a), "l"(b)); return r;
}

// ---------- volatile SMEM loads, [reg + literal] addressing ----------
// volatile: prevents CSE across planes / hoisting over barriers (round-3 bug).
#define LDSP(x, y, base, IMM)                                            \
    asm volatile("ld.shared.v2.u64 {%0, %1}, [%2+%3];"                   \
                 : "=l"(x), "=l"(y) : "r"(base), "n"(IMM))
#define LDS1(x, base, IMM)                                               \
    asm volatile("ld.shared.u64 %0, [%1+%2];"                            \
                 : "=l"(x) : "r"(base), "n"(IMM))

// Exact-erf GELU via A&S 7.1.26 (abs err ~1.5e-7, tol 1e-3).
__device__ __forceinline__ float gelu_exact(float x) {
    float z = x * 0.70710678118654752440f;
    float a = fabsf(z);
    float d = fmaf(0.3275911f, a, 1.0f);
    float t; asm("rcp.approx.f32 %0, %1;" : "=f"(t) : "f"(d));
    float p = fmaf(t, 1.061405429f, -1.453152027f);
    p = fmaf(t, p, 1.421413741f);
    p = fmaf(t, p, -0.284496736f);
    p = fmaf(t, p, 0.254829592f);
    p = p * t;
    float e; asm("ex2.approx.f32 %0, %1;" : "=f"(e) : "f"(-a * a * 1.4426950408889634f));
    float er = fmaf(-p, e, 1.0f);
    er = copysignf(er, z);
    return 0.5f * fmaf(x, er, x);
}

// Write one 16B chunk into both copies of a slab buffer.
// copyA: words wA..wA+3 (aligned v4).  copyB (shifted +1 word): wB..wB+3.
__device__ __forceinline__ void put(float* q, int wA, int wB, float4 v) {
    *(float4*)(q + wA) = v;
    q[wB] = v.x;
    *(float2*)(q + wB + 1) = make_float2(v.y, v.z);
    q[wB + 3] = v.w;
}

// One ky-row: windows arrive as aligned u64 pairs (no packing!).
// P1,P3 from copyA; P0,P2,P4 from shifted copyB.  Weights from SMEM triples.
#define ROW(SOFF, r, X0, X1, Y0, Y1, Z0, Z1)                                     \
    {                                                                            \
        u64 P0, P1, P2, P3, P4, wa, wb, wc;                                      \
        LDSP(P1, P3, rA, (SOFF) + (r) * RS * 4);                                 \
        LDSP(P0, P2, rA, (SOFF) + SLW * 4 + (r) * RS * 4);                       \
        LDS1(P4,     rA, (SOFF) + SLW * 4 + (r) * RS * 4 + 16);                  \
        LDSP(wa, wb, swa, (6 + (r)) * 32);                                       \
        LDS1(wc,     swa, (6 + (r)) * 32 + 16);                                  \
        fma2(X0, wa, P0); fma2(X1, wa, P2); fma2(X0, wb, P1);                    \
        fma2(X1, wb, P3); fma2(X0, wc, P2); fma2(X1, wc, P4);                    \
        LDSP(wa, wb, swa, (3 + (r)) * 32);                                       \
        LDS1(wc,     swa, (3 + (r)) * 32 + 16);                                  \
        fma2(Y0, wa, P0); fma2(Y1, wa, P2); fma2(Y0, wb, P1);                    \
        fma2(Y1, wb, P3); fma2(Y0, wc, P2); fma2(Y1, wc, P4);                    \
        LDSP(wa, wb, swa, (r) * 32);                                             \
        LDS1(wc,     swa, (r) * 32 + 16);                                        \
        if ((r) == 0) { mul2(Z0, wa, P0); mul2(Z1, wa, P2); }                    \
        else          { fma2(Z0, wa, P0); fma2(Z1, wa, P2); }                    \
        fma2(Z0, wb, P1); fma2(Z1, wb, P3); fma2(Z0, wc, P2); fma2(Z1, wc, P4);  \
    }

// One plane p: STS plane p+1 (both copies) into slab SF, LDG plane p+2,
// bar, 3 rows from slab SR (X completes out(p-1), Z fresh), store with center
// re-read from slab SC (holds plane p-1), bar2 protects SC from next fill.
#define BODY(SR, SF, SC, X0, X1, Y0, Y1, Z0, Z1, DOSTORE, DOLDG)                 \
    do {                                                                         \
        {                                                                        \
            float* q = sl + (SF) * BUFW;                                         \
            put(q, wA0, wB0, va);                                                \
            if (tid < 32) put(q, wA0 + 16 * RS, wB0 + 16 * RS, vb);              \
        }                                                                        \
        if (DOLDG) {                                                             \
            va = __ldg(pA); pA += stA;                                           \
            if (tid < 32) { vb = __ldg(pB); pB += stB; }                         \
        }                                                                        \
        __syncthreads();                                                         \
        ROW((SR) * BUFW * 4, 0, X0, X1, Y0, Y1, Z0, Z1)                          \
        ROW((SR) * BUFW * 4, 1, X0, X1, Y0, Y1, Z0, Z1)                          \
        ROW((SR) * BUFW * 4, 2, X0, X1, Y0, Y1, Z0, Z1)                          \
        if (DOSTORE) {                                                           \
            u64 c01, c23;                                                        \
            LDSP(c01, c23, rA, (SC) * BUFW * 4 + RS * 4);                        \
            u64 u0 = add2(X0, c01), u1 = add2(X1, c23);                          \
            float o0, o1, o2, o3;                                                \
            unpack2(u0, o0, o1); unpack2(u1, o2, o3);                            \
            o0 = gelu_exact(o0); o1 = gelu_exact(o1);                            \
            o2 = gelu_exact(o2); o3 = gelu_exact(o3);                            \
            asm volatile("st.global.v4.f32 [%0], {%1, %2, %3, %4};"              \
                         :: "l"(optr), "f"(o0), "f"(o1), "f"(o2), "f"(o3));      \
        }                                                                        \
        optr += 4096;                                                            \
        __syncthreads();                                                         \
    } while (0)

template<bool GUARD>
__global__ void __launch_bounds__(256, 4)
step_kernel(const float* __restrict__ in, float* __restrict__ out,
            const float* __restrict__ wts)
{
    const int tx  = threadIdx.x;             // 0..15 (w quads)
    const int ty  = threadIdx.y;             // 0..15 (h rows)
    const int tid = ty * 16 + tx;
    const int h0  = blockIdx.x * 16;
    const int c   = blockIdx.y;
    const int b   = blockIdx.z;

    const float* vin  = in  + (size_t)(b * CC + c) * VOL;
    float*       vout = out + (size_t)(b * CC + c) * VOL;

    // 3 buffers x (copyA + copyB) + weight pairs.
    __shared__ __align__(16) float sl[3 * BUFW];
    __shared__ __align__(16) u64   sw[36];

    if (tid < 27) {                          // weights as (w,w) pairs, 32B triples
        int kz = tid / 9, ky = (tid % 9) / 3, kx = tid % 3;
        float w = __ldg(&wts[c * 27 + tid]);
        sw[(kz * 3 + ky) * 4 + kx] = pack2(w, w);
    }
    if (tid < 216) {                         // zero W-halos: A words 3/68, B words 4/69
        int buf = tid / 72, k = tid % 72;
        int cp = k / 36, j = k % 36;
        int row = j % 18;
        int word = cp == 0 ? (j < 18 ? 3 : 68) : (j < 18 ? 4 : 69);
        sl[buf * BUFW + cp * SLW + row * RS + word] = 0.f;
    }

    const u32 sbase = (u32)__cvta_generic_to_shared(sl);
    const u32 swa   = (u32)__cvta_generic_to_shared(sw);
    const u32 rA    = sbase + (ty * RS + 4 + 4 * tx) * 4;

    // Loaders: thread tid handles 16B chunk (row r0, quad cq); tid<32 also row r0+16.
    const int r0 = tid >> 4, cq = tid & 15;
    const int gh0 = h0 - 1 + r0;
    const bool v0 = (gh0 >= 0) && (gh0 < 64);
    const float4* pA = v0 ? (const float4*)vin + gh0 * 16 + cq : &g_zero4;
    const int stA = v0 ? 1024 : 0;

    const int gh1 = h0 + 15 + r0;
    const bool v1 = (tid < 32) && (gh1 < 64);
    const float4* pB = v1 ? (const float4*)vin + gh1 * 16 + cq : &g_zero4;
    const int stB = v1 ? 1024 : 0;

    const int wA0 = r0 * RS + 4 + 4 * cq;          // copyA dst (words)
    const int wB0 = SLW + r0 * RS + 5 + 4 * cq;    // copyB dst (shifted +1)

    // Prologue: plane 0 -> slab 0; prefetch plane 1.
    float4 va = __ldg(pA); pA += stA;
    float4 vb = make_float4(0.f, 0.f, 0.f, 0.f);
    if (tid < 32) { vb = __ldg(pB); pB += stB; }
    put(sl, wA0, wB0, va);
    if (tid < 32) put(sl, wA0 + 16 * RS, wB0 + 16 * RS, vb);
    va = __ldg(pA); pA += stA;
    if (tid < 32) { vb = __ldg(pB); pB += stB; }

    u64 a00=0,a01=0,a10=0,a11=0,a20=0,a21=0;       // rotating accumulators

    float* optr = vout + ((h0 + ty) * 64 + 4 * tx) - 4096;

    // BODY(p): SR=p%3, SF=(p+1)%3, SC=(p+2)%3; X=a[(p+1)%3], Y=a[(p+2)%3], Z=a[p%3].
    BODY(0, 1, 2, a10,a11, a20,a21, a00,a01, false, true);     // p=0

#pragma unroll 1
    for (int k = 0; k < 21; ++k) {                              // p = 3k+1 .. 3k+3
        const bool g = !GUARD || (k < 20);
        BODY(1, 2, 0, a20,a21, a00,a01, a10,a11, true, true);   // p=3k+1 (ldg<=63 always)
        BODY(2, 0, 1, a00,a01, a10,a11, a20,a21, true, g);      // p=3k+2
        BODY(0, 1, 2, a10,a11, a20,a21, a00,a01, true, g);      // p=3k+3
    }

    // out(63): kz=2 contribution is zero padding; acc = a2; center in slab 0.
    {
        u64 c01, c23;
        LDSP(c01, c23, rA, RS * 4);                             // slab 0, row ty+1
        u64 u0 = add2(a20, c01), u1 = add2(a21, c23);
        float o0, o1, o2, o3;
        unpack2(u0, o0, o1); unpack2(u1, o2, o3);
        o0 = gelu_exact(o0); o1 = gelu_exact(o1);
        o2 = gelu_exact(o2); o3 = gelu_exact(o3);
        asm volatile("st.global.v4.f32 [%0], {%1, %2, %3, %4};"
                     :: "l"(optr), "f"(o0), "f"(o1), "f"(o2), "f"(o3));
    }
}

extern "C" void kernel_launch(void* const* d_in, const int* in_sizes, int n_in,
                              void* d_out, int out_size)
{
    const float* x = (const float*)d_in[0];
    const float* w = (const float*)d_in[1];
    float* out = (float*)d_out;

    float *sA = nullptr, *sB = nullptr;
    cudaGetSymbolAddress((void**)&sA, g_sA);
    cudaGetSymbolAddress((void**)&sB, g_sB);

    dim3 grid(4, CC, 4);
    dim3 blk(16, 16);

    // Step 0 reads the harness buffer (GUARD suppresses OOB prefetch);
    // steps 1..7 read 2-plane-padded scratch (unguarded prefetch).
    step_kernel<true ><<<grid, blk>>>(x,  sA,  w);
    step_kernel<false><<<grid, blk>>>(sA, sB,  w);
    step_kernel<false><<<grid, blk>>>(sB, sA,  w);
    step_kernel<false><<<grid, blk>>>(sA, sB,  w);
    step_kernel<false><<<grid, blk>>>(sB, sA,  w);
    step_kernel<false><<<grid, blk>>>(sA, sB,  w);
    step_kernel<false><<<grid, blk>>>(sB, sA,  w);
    step_kernel<false><<<grid, blk>>>(sA, out, w);
}

// round 7
// speedup vs baseline: 1.1846x; 1.1846x over previous
#include <cuda_runtime.h>

// x <- gelu(x + depthwise_conv3d_3x3x3(x)) x8.  [4,32,64,64,64] fp32.

#define CC    32
#define VOL   (64*64*64)
#define RS    72                 // words per slab row
#define RSB   (RS*4)             // bytes per slab row (288)
#define SLW   (18*RS)            // words per copy (18 rows)
#define SLW4  (SLW*4)            // bytes per copy (5184)
#define BUFW  (2*SLW)            // words per slab buffer (copyA + shifted copyB)
#define BUF4  (BUFW*4)           // bytes per slab buffer (10368)

typedef unsigned long long u64;
typedef unsigned int u32;

// Ping-pong scratches padded one plane (plane-64 prefetch lands in padding).
__device__ float  g_sA[4 * CC * VOL + 4096];
__device__ float  g_sB[4 * CC * VOL + 4096];
__device__ __align__(16) float4 g_zero4 = {0.f, 0.f, 0.f, 0.f};

// ---------- packed f32x2 helpers ----------
__device__ __forceinline__ u64 pack2(float lo, float hi) {
    u64 r; asm("mov.b64 %0, {%1, %2};" : "=l"(r) : "f"(lo), "f"(hi)); return r;
}
__device__ __forceinline__ void unpack2(u64 v, float& lo, float& hi) {
    asm("mov.b64 {%0, %1}, %2;" : "=f"(lo), "=f"(hi) : "l"(v));
}
__device__ __forceinline__ void fma2(u64& acc, u64 a, u64 b) {
    asm("fma.rn.f32x2 %0, %1, %2, %0;" : "+l"(acc) : "l"(a), "l"(b));
}
__device__ __forceinline__ void mul2(u64& d, u64 a, u64 b) {
    asm("mul.rn.f32x2 %0, %1, %2;" : "=l"(d) : "l"(a), "l"(b));
}
__device__ __forceinline__ u64 add2(u64 a, u64 b) {
    u64 r; asm("add.rn.f32x2 %0, %1, %2;" : "=l"(r) : "l"(a), "l"(b)); return r;
}

// ---------- volatile SMEM loads, [reg + imm] ----------
// volatile: blocks CSE across planes (addresses repeat every 2 planes) and
// hoisting over __syncthreads — the round-3 bug class.
#define LDSP(x, y, base, IMM)                                            \
    asm volatile("ld.shared.v2.u64 {%0, %1}, [%2+%3];"                   \
                 : "=l"(x), "=l"(y) : "r"(base), "n"(IMM))
#define LDS1(x, base, IMM)                                               \
    asm volatile("ld.shared.u64 %0, [%1+%2];"                            \
                 : "=l"(x) : "r"(base), "n"(IMM))

// Exact-erf GELU via A&S 7.1.26 (abs err ~1.5e-7, tol 1e-3).
__device__ __forceinline__ float gelu_exact(float x) {
    float z = x * 0.70710678118654752440f;
    float a = fabsf(z);
    float d = fmaf(0.3275911f, a, 1.0f);
    float t; asm("rcp.approx.f32 %0, %1;" : "=f"(t) : "f"(d));
    float p = fmaf(t, 1.061405429f, -1.453152027f);
    p = fmaf(t, p, 1.421413741f);
    p = fmaf(t, p, -0.284496736f);
    p = fmaf(t, p, 0.254829592f);
    p = p * t;
    float e; asm("ex2.approx.f32 %0, %1;" : "=f"(e) : "f"(-a * a * 1.4426950408889634f));
    float er = fmaf(-p, e, 1.0f);
    er = copysignf(er, z);
    return 0.5f * fmaf(x, er, x);
}

// One ky-row: all windows arrive as aligned u64 (no packing, no weight LDS).
// copyA u64s -> P1,P3 ; shifted copyB u64s -> P0,P2,P4. Weights from registers.
#define ROW(SB, r, FIRSTZ, CAPC)                                                 \
    {                                                                            \
        u64 P0, P1, P2, P3, P4;                                                  \
        LDSP(P1, P3, rA, (SB) + (r) * RSB);                                      \
        LDSP(P0, P2, rA, (SB) + SLW4 + (r) * RSB);                               \
        LDS1(P4,     rA, (SB) + SLW4 + (r) * RSB + 16);                          \
        if (CAPC) { CN0 = P1; CN1 = P3; }                                        \
        fma2(X0, W2[18 + (r)*3 + 0], P0); fma2(X1, W2[18 + (r)*3 + 0], P2);      \
        fma2(X0, W2[18 + (r)*3 + 1], P1); fma2(X1, W2[18 + (r)*3 + 1], P3);      \
        fma2(X0, W2[18 + (r)*3 + 2], P2); fma2(X1, W2[18 + (r)*3 + 2], P4);      \
        fma2(Y0, W2[ 9 + (r)*3 + 0], P0); fma2(Y1, W2[ 9 + (r)*3 + 0], P2);      \
        fma2(Y0, W2[ 9 + (r)*3 + 1], P1); fma2(Y1, W2[ 9 + (r)*3 + 1], P3);      \
        fma2(Y0, W2[ 9 + (r)*3 + 2], P2); fma2(Y1, W2[ 9 + (r)*3 + 2], P4);      \
        if (FIRSTZ) { mul2(Z0, W2[(r)*3 + 0], P0); mul2(Z1, W2[(r)*3 + 0], P2);} \
        else        { fma2(Z0, W2[(r)*3 + 0], P0); fma2(Z1, W2[(r)*3 + 0], P2);} \
        fma2(Z0, W2[(r)*3 + 1], P1); fma2(Z1, W2[(r)*3 + 1], P3);                \
        fma2(Z0, W2[(r)*3 + 2], P2); fma2(Z1, W2[(r)*3 + 2], P4);                \
    }

// One plane P: STS prefetched plane P (both copies) into slab AA/AB, prefetch
// plane P+1, barrier, 3 rows from same slab (X completes out(P-1)), store.
#define BODY(P, AA, AB, SB, _X0,_X1,_Y0,_Y1,_Z0,_Z1, CP0,CP1, _CN0,_CN1, DOSTORE)\
    do {                                                                         \
        *(float4*)(AA) = va;                                                     \
        (AB)[0] = va.x;                                                          \
        *(float2*)((AB) + 1) = make_float2(va.y, va.z);                          \
        (AB)[3] = va.w;                                                          \
        if (tid < 32) {                                                          \
            *(float4*)((AA) + 16 * RS) = vb;                                     \
            (AB)[16 * RS]     = vb.x;                                            \
            *(float2*)((AB) + 16 * RS + 1) = make_float2(vb.y, vb.z);            \
            (AB)[16 * RS + 3] = vb.w;                                            \
        }                                                                        \
        if (!GUARD || (P) < 63) {                                                \
            va = __ldg(pA); pA += stA;                                           \
            if (tid < 32) { vb = __ldg(pB); pB += stB; }                         \
        }                                                                        \
        __syncthreads();                                                         \
        {                                                                        \
            u64 &X0=_X0, &X1=_X1, &Y0=_Y0, &Y1=_Y1, &Z0=_Z0, &Z1=_Z1;           \
            u64 &CN0=_CN0, &CN1=_CN1;                                            \
            ROW(SB, 0, true,  false)                                             \
            ROW(SB, 1, false, true)                                              \
            ROW(SB, 2, false, false)                                             \
            if (DOSTORE) {                                                       \
                u64 u0 = add2(X0, CP0), u1 = add2(X1, CP1);                      \
                float o0, o1, o2, o3;                                            \
                unpack2(u0, o0, o1); unpack2(u1, o2, o3);                        \
                float4 ov = make_float4(gelu_exact(o0), gelu_exact(o1),          \
                                        gelu_exact(o2), gelu_exact(o3));         \
                *(float4*)optr = ov;                                             \
            }                                                                    \
        }                                                                        \
        optr += 4096;   /* one D-plane = 4096 FLOATS (r6 bug: was 4096 bytes) */ \
    } while (0)

template<bool GUARD>
__global__ void __launch_bounds__(256, 2)
step_kernel(const float* __restrict__ in, float* __restrict__ out,
            const float* __restrict__ wts)
{
    const int tx  = threadIdx.x;             // 0..15 (w quads)
    const int ty  = threadIdx.y;             // 0..15 (h rows)
    const int tid = ty * 16 + tx;
    const int h0  = blockIdx.x * 16;
    const int c   = blockIdx.y;
    const int b   = blockIdx.z;

    const float* vin  = in  + (size_t)(b * CC + c) * VOL;
    float*       vout = out + (size_t)(b * CC + c) * VOL;

    // 27 weights duplicated into f32x2 register pairs (uniform per block).
    u64 W2[27];
#pragma unroll
    for (int i = 0; i < 27; ++i) {
        float w = __ldg(&wts[c * 27 + i]);
        W2[i] = pack2(w, w);
    }

    // 2 ping-pong slab buffers, each = copyA(18x72) + copyB shifted +1 word.
    // copyA: words 4..67 = in[0..63], halo 3/68 = 0.
    // copyB: words 5..68 = in[0..63], halo 4/69 = 0.
    __shared__ __align__(16) float sl[2 * BUFW];

    if (tid < 144) {                         // zero W-halo words of both slabs
        int buf = tid / 72, k = tid % 72;
        int cp  = k / 36, j = k % 36;
        int row = j % 18;
        int word = cp ? (j < 18 ? 4 : 69) : (j < 18 ? 3 : 68);
        sl[buf * BUFW + cp * SLW + row * RS + word] = 0.f;
    }

    const u32 sbase = (u32)__cvta_generic_to_shared(sl);
    const u32 rA    = sbase + (ty * RS + 4 + 4 * tx) * 4;

    // Loaders: thread tid owns 16B chunk (slab row r0, quad cq); tid<32 also row r0+16.
    const int r0 = tid >> 4, cq = tid & 15;
    const int gh0 = h0 - 1 + r0;
    const bool v0 = (gh0 >= 0) && (gh0 < 64);
    const float4* pA = v0 ? (const float4*)vin + gh0 * 16 + cq : &g_zero4;
    const int stA = v0 ? 1024 : 0;

    const int gh1 = h0 + 15 + r0;            // rows 16,17 (tid<32)
    const bool v1 = (tid < 32) && (gh1 < 64);
    const float4* pB = v1 ? (const float4*)vin + gh1 * 16 + cq : &g_zero4;
    const int stB = v1 ? 1024 : 0;

    // STS destinations (slab 0 / slab 1), copyA (aligned) and copyB (+1 word).
    float* a0A = sl + (r0 * RS + 4 + 4 * cq);
    float* a0B = sl + (SLW + r0 * RS + 5 + 4 * cq);
    float* a1A = a0A + BUFW;
    float* a1B = a0B + BUFW;

    // Prologue: load plane 0.
    float4 va = __ldg(pA); pA += stA;
    float4 vb = make_float4(0.f, 0.f, 0.f, 0.f);
    if (tid < 32) { vb = __ldg(pB); pB += stB; }

    u64 x0=0,x1=0,y0=0,y1=0,z0=0,z1=0;       // rotating accumulators (static roles)
    u64 cA0=0,cA1=0,cB0=0,cB1=0;             // rotating residual centers

    float* optr = vout + ((h0 + ty) * 64 + 4 * tx) - 4096;   // float units!

    // Peel planes 0..3 (period-6: slab %2, roles %3, centers %2).
    BODY(0, a0A, a0B, 0,    x0,x1,y0,y1,z0,z1, cA0,cA1, cB0,cB1, false);
    BODY(1, a1A, a1B, BUF4, y0,y1,z0,z1,x0,x1, cB0,cB1, cA0,cA1, true);
    BODY(2, a0A, a0B, 0,    z0,z1,x0,x1,y0,y1, cA0,cA1, cB0,cB1, true);
    BODY(3, a1A, a1B, BUF4, x0,x1,y0,y1,z0,z1, cB0,cB1, cA0,cA1, true);

#pragma unroll 1
    for (int i = 0; i < 10; ++i) {           // planes 4..63
        const int p = 4 + 6 * i;
        BODY(p+0, a0A, a0B, 0,    y0,y1,z0,z1,x0,x1, cA0,cA1, cB0,cB1, true);
        BODY(p+1, a1A, a1B, BUF4, z0,z1,x0,x1,y0,y1, cB0,cB1, cA0,cA1, true);
        BODY(p+2, a0A, a0B, 0,    x0,x1,y0,y1,z0,z1, cA0,cA1, cB0,cB1, true);
        BODY(p+3, a1A, a1B, BUF4, y0,y1,z0,z1,x0,x1, cB0,cB1, cA0,cA1, true);
        BODY(p+4, a0A, a0B, 0,    z0,z1,x0,x1,y0,y1, cA0,cA1, cB0,cB1, true);
        BODY(p+5, a1A, a1B, BUF4, x0,x1,y0,y1,z0,z1, cB0,cB1, cA0,cA1, true);
    }

    // out(63): kz=2 contribution (plane 64) is zero padding; partial in y, center cA.
    {
        u64 u0 = add2(y0, cA0), u1 = add2(y1, cA1);
        float o0, o1, o2, o3;
        unpack2(u0, o0, o1); unpack2(u1, o2, o3);
        float4 ov = make_float4(gelu_exact(o0), gelu_exact(o1),
                                gelu_exact(o2), gelu_exact(o3));
        *(float4*)optr = ov;
    }
}

extern "C" void kernel_launch(void* const* d_in, const int* in_sizes, int n_in,
                              void* d_out, int out_size)
{
    const float* x = (const float*)d_in[0];
    const float* w = (const float*)d_in[1];
    float* out = (float*)d_out;

    float *sA = nullptr, *sB = nullptr;
    cudaGetSymbolAddress((void**)&sA, g_sA);
    cudaGetSymbolAddress((void**)&sB, g_sB);

    dim3 grid(4, CC, 4);
    dim3 blk(16, 16);

    // Step 0 reads the harness buffer (GUARD skips the plane-64 prefetch);
    // steps 1..7 read padded scratch (unguarded prefetch into padding).
    step_kernel<true ><<<grid, blk>>>(x,  sA,  w);
    step_kernel<false><<<grid, blk>>>(sA, sB,  w);
    step_kernel<false><<<grid, blk>>>(sB, sA,  w);
    step_kernel<false><<<grid, blk>>>(sA, sB,  w);
    step_kernel<false><<<grid, blk>>>(sB, sA,  w);
    step_kernel<false><<<grid, blk>>>(sA, sB,  w);
    step_kernel<false><<<grid, blk>>>(sB, sA,  w);
    step_kernel<false><<<grid, blk>>>(sA, out, w);
}

// round 8
// speedup vs baseline: 1.2349x; 1.0425x over previous
#include <cuda_runtime.h>

// x <- gelu(x + depthwise_conv3d_3x3x3(x)) x8.  [4,32,64,64,64] fp32.
// 2 planes per barrier window: 32 windows instead of 64 barriers.

#define CC    32
#define VOL   (64*64*64)
#define RS    72                 // words per slab row
#define RSB   (RS*4)             // bytes per slab row
#define SLW   (18*RS)            // words per copy (18 rows)
#define SLW4  (SLW*4)            // bytes per copy
#define PAIRW (4*SLW)            // words per buffer: 2 planes x (copyA+copyB)
#define PAIR4 (PAIRW*4)          // bytes per buffer

typedef unsigned long long u64;
typedef unsigned int u32;

// Ping-pong scratches (no padding needed: last window skips prefetch).
__device__ float  g_sA[4 * CC * VOL];
__device__ float  g_sB[4 * CC * VOL];
__device__ __align__(16) float4 g_zero4 = {0.f, 0.f, 0.f, 0.f};

// ---------- packed f32x2 helpers ----------
__device__ __forceinline__ u64 pack2(float lo, float hi) {
    u64 r; asm("mov.b64 %0, {%1, %2};" : "=l"(r) : "f"(lo), "f"(hi)); return r;
}
__device__ __forceinline__ void unpack2(u64 v, float& lo, float& hi) {
    asm("mov.b64 {%0, %1}, %2;" : "=f"(lo), "=f"(hi) : "l"(v));
}
__device__ __forceinline__ void fma2(u64& acc, u64 a, u64 b) {
    asm("fma.rn.f32x2 %0, %1, %2, %0;" : "+l"(acc) : "l"(a), "l"(b));
}
__device__ __forceinline__ void mul2(u64& d, u64 a, u64 b) {
    asm("mul.rn.f32x2 %0, %1, %2;" : "=l"(d) : "l"(a), "l"(b));
}
__device__ __forceinline__ u64 add2(u64 a, u64 b) {
    u64 r; asm("add.rn.f32x2 %0, %1, %2;" : "=l"(r) : "l"(a), "l"(b)); return r;
}

// ---------- volatile SMEM loads (block CSE / hoisting over barriers) ----------
#define LDSP(x, y, base, IMM)                                            \
    asm volatile("ld.shared.v2.u64 {%0, %1}, [%2+%3];"                   \
                 : "=l"(x), "=l"(y) : "r"(base), "n"(IMM))
#define LDS1(x, base, IMM)                                               \
    asm volatile("ld.shared.u64 %0, [%1+%2];"                            \
                 : "=l"(x) : "r"(base), "n"(IMM))

// Exact-erf GELU via A&S 7.1.26 (abs err ~1.5e-7, tol 1e-3).
__device__ __forceinline__ float gelu_exact(float x) {
    float z = x * 0.70710678118654752440f;
    float a = fabsf(z);
    float d = fmaf(0.3275911f, a, 1.0f);
    float t; asm("rcp.approx.f32 %0, %1;" : "=f"(t) : "f"(d));
    float p = fmaf(t, 1.061405429f, -1.453152027f);
    p = fmaf(t, p, 1.421413741f);
    p = fmaf(t, p, -0.284496736f);
    p = fmaf(t, p, 0.254829592f);
    p = p * t;
    float e; asm("ex2.approx.f32 %0, %1;" : "=f"(e) : "f"(-a * a * 1.4426950408889634f));
    float er = fmaf(-p, e, 1.0f);
    er = copysignf(er, z);
    return 0.5f * fmaf(x, er, x);
}

// Store one 16B chunk into copyA (aligned) and shifted copyB of a plane.
// off is compile-time -> STS [R+imm].
__device__ __forceinline__ void put_pair(float* aA, int off, float4 v) {
    *(float4*)(aA + off) = v;
    float* aB = aA + off + SLW + 1;
    aB[0] = v.x;
    *(float2*)(aB + 1) = make_float2(v.y, v.z);
    aB[3] = v.w;
}

// One ky-row of one plane (byte offset SB): windows arrive as aligned u64.
// X completes out(q-1) [kz2 wts], Y mid [kz1], Z fresh-at-row0 [kz0].
#define ROW(SB, r, X0,X1, Y0,Y1, Z0,Z1, FIRSTZ, CAPC)                            \
    {                                                                            \
        u64 P0, P1, P2, P3, P4;                                                  \
        LDSP(P1, P3, rA, (SB) + (r) * RSB);                                      \
        LDSP(P0, P2, rA, (SB) + SLW4 + (r) * RSB);                               \
        LDS1(P4,     rA, (SB) + SLW4 + (r) * RSB + 16);                          \
        if (CAPC) { cenA0 = P1; cenA1 = P3; }                                    \
        fma2(X0, W2[18 + (r)*3 + 0], P0); fma2(X1, W2[18 + (r)*3 + 0], P2);      \
        fma2(X0, W2[18 + (r)*3 + 1], P1); fma2(X1, W2[18 + (r)*3 + 1], P3);      \
        fma2(X0, W2[18 + (r)*3 + 2], P2); fma2(X1, W2[18 + (r)*3 + 2], P4);      \
        fma2(Y0, W2[ 9 + (r)*3 + 0], P0); fma2(Y1, W2[ 9 + (r)*3 + 0], P2);      \
        fma2(Y0, W2[ 9 + (r)*3 + 1], P1); fma2(Y1, W2[ 9 + (r)*3 + 1], P3);      \
        fma2(Y0, W2[ 9 + (r)*3 + 2], P2); fma2(Y1, W2[ 9 + (r)*3 + 2], P4);      \
        if (FIRSTZ) { mul2(Z0, W2[(r)*3 + 0], P0); mul2(Z1, W2[(r)*3 + 0], P2);} \
        else        { fma2(Z0, W2[(r)*3 + 0], P0); fma2(Z1, W2[(r)*3 + 0], P2);} \
        fma2(Z0, W2[(r)*3 + 1], P1); fma2(Z1, W2[(r)*3 + 1], P3);                \
        fma2(Z0, W2[(r)*3 + 2], P2); fma2(Z1, W2[(r)*3 + 2], P4);                \
    }

#define STORE4(ACC0, ACC1, C0, C1, PTR)                                          \
    {                                                                            \
        u64 u0 = add2(ACC0, C0), u1 = add2(ACC1, C1);                            \
        float o0, o1, o2, o3;                                                    \
        unpack2(u0, o0, o1); unpack2(u1, o2, o3);                                \
        float4 ov = make_float4(gelu_exact(o0), gelu_exact(o1),                  \
                                gelu_exact(o2), gelu_exact(o3));                 \
        *(float4*)(PTR) = ov;                                                    \
    }

// Window k: planes p=2k (even) and p+1 in buffer at byte SB / word WOFF.
// STS registers (pair k), prefetch pair k+1, ONE barrier, compute 6 rows.
// A completes at plane p -> store out(p-1); B completes at plane p+1 ->
// store out(p) with center re-read from resident plane p; capture cenA
// (center of plane p+1) for next window; C, D carry.
#define WINDOW(SB, WOFF, A0,A1, B0,B1, C0,C1, D0,D1, DOST0, DOPF)                \
    do {                                                                         \
        put_pair(aA, (WOFF),                 va0);                               \
        put_pair(aA, (WOFF) + 2*SLW,         va1);                               \
        if (tid < 32) {                                                          \
            put_pair(aA, (WOFF) + 16*RS,         vb0);                           \
            put_pair(aA, (WOFF) + 2*SLW + 16*RS, vb1);                           \
        }                                                                        \
        if (DOPF) {                                                              \
            va0 = __ldg(pA); va1 = __ldg(pA + stP); pA += 2 * stP;               \
            if (tid < 32) { vb0 = __ldg(pB); vb1 = __ldg(pB + stQ);              \
                            pB += 2 * stQ; }                                     \
        }                                                                        \
        __syncthreads();                                                         \
        ROW((SB),            0, A0,A1, B0,B1, C0,C1, true,  false)               \
        ROW((SB),            1, A0,A1, B0,B1, C0,C1, false, false)               \
        ROW((SB),            2, A0,A1, B0,B1, C0,C1, false, false)               \
        if (DOST0) STORE4(A0, A1, cenA0, cenA1, optr);                           \
        ROW((SB) + 2*SLW4,   0, B0,B1, C0,C1, D0,D1, true,  false)               \
        ROW((SB) + 2*SLW4,   1, B0,B1, C0,C1, D0,D1, false, true)                \
        ROW((SB) + 2*SLW4,   2, B0,B1, C0,C1, D0,D1, false, false)               \
        {                                                                        \
            u64 c01, c23;                                                        \
            LDSP(c01, c23, rA, (SB) + RSB);                                      \
            STORE4(B0, B1, c01, c23, optr + 4096);                               \
        }                                                                        \
        optr += 8192;                                                            \
    } while (0)

__global__ void __launch_bounds__(256, 2)
step_kernel(const float* __restrict__ in, float* __restrict__ out,
            const float* __restrict__ wts)
{
    const int tx  = threadIdx.x;             // 0..15 (w quads)
    const int ty  = threadIdx.y;             // 0..15 (h rows)
    const int tid = ty * 16 + tx;
    const int h0  = blockIdx.x * 16;
    const int c   = blockIdx.y;
    const int b   = blockIdx.z;

    const float* vin  = in  + (size_t)(b * CC + c) * VOL;
    float*       vout = out + (size_t)(b * CC + c) * VOL;

    // 27 weights duplicated into f32x2 register pairs.
    u64 W2[27];
#pragma unroll
    for (int i = 0; i < 27; ++i) {
        float w = __ldg(&wts[c * 27 + i]);
        W2[i] = pack2(w, w);
    }

    // 2 double-buffered plane-pair buffers. Layout per buffer:
    // [plane0 copyA][plane0 copyB(+1)][plane1 copyA][plane1 copyB(+1)].
    __shared__ __align__(16) float sl[2 * PAIRW];

    // Zero all W-halo words: copyA {3,68}, copyB {4,69}, 18 rows, 4 plane-copies x2.
    for (int i = tid; i < 288; i += 256) {
        int buf = i / 144, r1 = i % 144;
        int q   = r1 / 72,  j  = r1 % 72;
        int cp  = j / 36,   k2 = j % 36;
        int row = k2 % 18,  hi = k2 / 18;
        int word = cp ? (hi ? 69 : 4) : (hi ? 68 : 3);
        sl[buf * PAIRW + q * 2 * SLW + cp * SLW + row * RS + word] = 0.f;
    }

    const u32 sbase = (u32)__cvta_generic_to_shared(sl);
    const u32 rA    = sbase + (ty * RS + 4 + 4 * tx) * 4;

    // Loaders: thread owns 16B chunk (slab row r0, quad cq); tid<32 also row r0+16.
    const int r0 = tid >> 4, cq = tid & 15;
    const int gh0 = h0 - 1 + r0;
    const bool v0 = (gh0 >= 0) && (gh0 < 64);
    const float4* pA = v0 ? (const float4*)vin + gh0 * 16 + cq : &g_zero4;
    const int stP = v0 ? 1024 : 0;           // one plane, float4 units

    const int gh1 = h0 + 15 + r0;            // rows 16,17 (tid<32)
    const bool v1 = (tid < 32) && (gh1 < 64);
    const float4* pB = v1 ? (const float4*)vin + gh1 * 16 + cq : &g_zero4;
    const int stQ = v1 ? 1024 : 0;

    float* aA = sl + (r0 * RS + 4 + 4 * cq); // STS base (buffer0 plane0 copyA)

    // Prologue: load plane pair 0 (planes 0,1).
    float4 va0 = __ldg(pA), va1 = __ldg(pA + stP); pA += 2 * stP;
    float4 vb0 = make_float4(0.f, 0.f, 0.f, 0.f), vb1 = vb0;
    if (tid < 32) { vb0 = __ldg(pB); vb1 = __ldg(pB + stQ); pB += 2 * stQ; }

    // 4 rotating accumulator pairs + carried center pair.
    u64 a00=0,a01=0, a10=0,a11=0, a20=0,a21=0, a30=0,a31=0;
    u64 cenA0=0, cenA1=0;

    float* optr = vout + ((h0 + ty) * 64 + 4 * tx) - 4096;   // float units

    // Window roles, period 2: even (A,B,C,D)=(a0,a1,a2,a3); odd =(a2,a3,a0,a1).
    WINDOW(0,     0,     a00,a01, a10,a11, a20,a21, a30,a31, false, true);  // w0
    WINDOW(PAIR4, PAIRW, a20,a21, a30,a31, a00,a01, a10,a11, true,  true);  // w1
#pragma unroll 1
    for (int i = 0; i < 14; ++i) {                                          // w2..w29
        WINDOW(0,     0,     a00,a01, a10,a11, a20,a21, a30,a31, true, true);
        WINDOW(PAIR4, PAIRW, a20,a21, a30,a31, a00,a01, a10,a11, true, true);
    }
    WINDOW(0,     0,     a00,a01, a10,a11, a20,a21, a30,a31, true, true);   // w30
    WINDOW(PAIR4, PAIRW, a20,a21, a30,a31, a00,a01, a10,a11, true, false);  // w31

    // out(63): kz2 (plane 64) is zero; partial lives in a0 (C of w31),
    // center = cenA captured at w31's plane 63.
    STORE4(a00, a01, cenA0, cenA1, optr);
}

extern "C" void kernel_launch(void* const* d_in, const int* in_sizes, int n_in,
                              void* d_out, int out_size)
{
    const float* x = (const float*)d_in[0];
    const float* w = (const float*)d_in[1];
    float* out = (float*)d_out;

    float *sA = nullptr, *sB = nullptr;
    cudaGetSymbolAddress((void**)&sA, g_sA);
    cudaGetSymbolAddress((void**)&sB, g_sB);

    dim3 grid(4, CC, 4);
    dim3 blk(16, 16);

    step_kernel<<<grid, blk>>>(x,  sA,  w);
    step_kernel<<<grid, blk>>>(sA, sB,  w);
    step_kernel<<<grid, blk>>>(sB, sA,  w);
    step_kernel<<<grid, blk>>>(sA, sB,  w);
    step_kernel<<<grid, blk>>>(sB, sA,  w);
    step_kernel<<<grid, blk>>>(sA, sB,  w);
    step_kernel<<<grid, blk>>>(sB, sA,  w);
    step_kernel<<<grid, blk>>>(sA, out, w);
}